// round 2
// baseline (speedup 1.0000x reference)
#include <cuda_runtime.h>
#include <math.h>

// Problem constants: x is [B=4, M=2048, N=2048] float32.
// out[b,u,v] = sum_{p,q} x[b,p,q] * sin(pi*(2u+1)*p/(2M)) * cos(pi*(2v+1)*q/(2N))
#define NN2048 2048
#define BB4 4

// Scratch (device globals: allocation-free rule).
__device__ float g_C[NN2048 * NN2048];                     // C[v,q] = cos(pi*(2v+1)*q/4096)
__device__ float g_S[NN2048 * NN2048];                     // S[u,p] = sin(pi*(2u+1)*p/4096)
__device__ float g_T[(size_t)BB4 * NN2048 * NN2048];       // intermediate t[b,p,v]

// -------------------------------------------------------------------------
// Basis generation. (2v+1)*q <= 4095*2047 < 2^24 so the fp32 argument is
// exact; cospif/sinpif do proper pi-based range reduction (≈1 ulp).
// -------------------------------------------------------------------------
__global__ void gen_basis_kernel() {
    int idx = blockIdx.x * blockDim.x + threadIdx.x;
    if (idx >= NN2048 * NN2048) return;
    int v = idx >> 11;          // / 2048
    int q = idx & 2047;         // % 2048
    float a = (float)((2 * v + 1) * q) * (1.0f / 4096.0f);
    g_C[idx] = cospif(a);
    g_S[idx] = sinpif(a);
}

// -------------------------------------------------------------------------
// Tiled SGEMM: 128x128 block tile, BK=8, 256 threads, 8x8 register microtile.
//   BT = true :  Cm[i,j] = sum_k A[i,k] * Bm[j,k]   (both K-contiguous, "NT")
//   BT = false:  Cm[i,j] = sum_k A[i,k] * Bm[k,j]   ("NN")
// Batched over blockIdx.z with per-operand strides (stride 0 = shared operand).
// All dims are multiples of 128 -> no bounds checks.
// -------------------------------------------------------------------------
template <bool BT>
__global__ void __launch_bounds__(256)
sgemm_kernel(const float* __restrict__ A, const float* __restrict__ Bm,
             float* __restrict__ Cm, int M, int N, int K,
             size_t strideA, size_t strideB, size_t strideC)
{
    __shared__ float As[8][132];   // stride 132 (multiple of 4): conflict-free
    __shared__ float Bs[8][132];   // scatter stores + aligned float4 access

    A  += (size_t)blockIdx.z * strideA;
    Bm += (size_t)blockIdx.z * strideB;
    Cm += (size_t)blockIdx.z * strideC;

    const int tid  = threadIdx.x;
    const int brow = blockIdx.y * 128;
    const int bcol = blockIdx.x * 128;
    const int tx   = tid & 15;     // 16 column groups
    const int ty   = tid >> 4;     // 16 row groups

    // Tile-load indices: 128 rows x 8 k-cols = 256 float4, one per thread.
    const int lrow = tid >> 1;
    const int lcol = (tid & 1) << 2;

    float acc[8][8];
#pragma unroll
    for (int i = 0; i < 8; ++i)
#pragma unroll
        for (int j = 0; j < 8; ++j) acc[i][j] = 0.0f;

    for (int k0 = 0; k0 < K; k0 += 8) {
        // A tile: [128 rows x 8 k], transpose-scatter into As[k][row]
        float4 av = *(const float4*)(A + (size_t)(brow + lrow) * K + k0 + lcol);
        As[lcol + 0][lrow] = av.x;
        As[lcol + 1][lrow] = av.y;
        As[lcol + 2][lrow] = av.z;
        As[lcol + 3][lrow] = av.w;

        if (BT) {
            // B tile: [128 n-rows x 8 k], transpose-scatter into Bs[k][n]
            float4 bv = *(const float4*)(Bm + (size_t)(bcol + lrow) * K + k0 + lcol);
            Bs[lcol + 0][lrow] = bv.x;
            Bs[lcol + 1][lrow] = bv.y;
            Bs[lcol + 2][lrow] = bv.z;
            Bs[lcol + 3][lrow] = bv.w;
        } else {
            // B tile: [8 k-rows x 128 n], direct float4 into Bs[k][n]
            const int kr = tid >> 5;
            const int nc = (tid & 31) << 2;
            float4 bv = *(const float4*)(Bm + (size_t)(k0 + kr) * N + bcol + nc);
            *(float4*)&Bs[kr][nc] = bv;
        }
        __syncthreads();

#pragma unroll
        for (int kk = 0; kk < 8; ++kk) {
            float a[8], b[8];
            *(float4*)&a[0] = *(const float4*)&As[kk][ty * 8];
            *(float4*)&a[4] = *(const float4*)&As[kk][ty * 8 + 4];
            *(float4*)&b[0] = *(const float4*)&Bs[kk][tx * 8];
            *(float4*)&b[4] = *(const float4*)&Bs[kk][tx * 8 + 4];
#pragma unroll
            for (int i = 0; i < 8; ++i)
#pragma unroll
                for (int j = 0; j < 8; ++j)
                    acc[i][j] = fmaf(a[i], b[j], acc[i][j]);
        }
        __syncthreads();
    }

#pragma unroll
    for (int i = 0; i < 8; ++i) {
        float* outp = Cm + (size_t)(brow + ty * 8 + i) * N + bcol + tx * 8;
        float4 v0 = make_float4(acc[i][0], acc[i][1], acc[i][2], acc[i][3]);
        float4 v1 = make_float4(acc[i][4], acc[i][5], acc[i][6], acc[i][7]);
        *(float4*)outp       = v0;
        *(float4*)(outp + 4) = v1;
    }
}

// -------------------------------------------------------------------------
// Launch: gen basis -> T = X @ C^T (NT) -> Out_b = S @ T_b (NN).
// Graph-capturable: kernel launches only, no alloc, no sync.
// -------------------------------------------------------------------------
extern "C" void kernel_launch(void* const* d_in, const int* in_sizes, int n_in,
                              void* d_out, int out_size)
{
    const float* x   = (const float*)d_in[0];
    float*       out = (float*)d_out;

    float *pC, *pS, *pT;
    cudaGetSymbolAddress((void**)&pC, g_C);
    cudaGetSymbolAddress((void**)&pS, g_S);
    cudaGetSymbolAddress((void**)&pT, g_T);

    const size_t plane = (size_t)NN2048 * NN2048;

    // 1) Basis matrices (regenerated every call: deterministic, cheap ~8.4M elems)
    gen_basis_kernel<<<(NN2048 * NN2048 + 255) / 256, 256>>>();

    // 2) t[b,p,v] = sum_q x[b,p,q] * C[v,q]   ("NT": both K-contiguous)
    //    grid: 16 col-tiles x 16 row-tiles x 4 batches
    sgemm_kernel<true><<<dim3(16, 16, BB4), 256>>>(
        x, pC, pT, NN2048, NN2048, NN2048,
        /*strideA=*/plane, /*strideB=*/0, /*strideC=*/plane);

    // 3) out[b,u,v] = sum_p S[u,p] * t[b,p,v]   ("NN")
    sgemm_kernel<false><<<dim3(16, 16, BB4), 256>>>(
        pS, pT, out, NN2048, NN2048, NN2048,
        /*strideA=*/0, /*strideB=*/plane, /*strideC=*/plane);
}